// round 1
// baseline (speedup 1.0000x reference)
#include <cuda_runtime.h>
#include <cstdint>

// TemplatePairEmbedderMonomer — write-bound sparse-linear formulation.
// out[t,i,j,o] = b[o] + fm2d * ( W[o,bin(i,j)] + W[o,39]*pbm2 + W[o,40+aa_j]
//                              + W[o,62+aa_i] + W[o,84:87]·uv + W[o,87] )

#define N_RES 768
#define MAX_ROWS 8192

// Scratch (no dynamic allocation allowed)
__device__ float g_M[MAX_ROWS * 9];    // per-row rotation M (rigid_vec = M @ (ca_j - ca_i))
__device__ float g_PJ[MAX_ROWS * 12];  // {pbx,pby,pbz, cax,cay,caz, pbm, fm, aa_bits, 0,0,0}

__global__ __launch_bounds__(256) void precompute_kernel(
    const float* __restrict__ pos,      // [rows, 37, 3]
    const float* __restrict__ pb,       // [rows, 3]
    const float* __restrict__ pbm,      // [rows]
    const float* __restrict__ aamask,   // [rows, 37]
    const int*   __restrict__ aatype,   // [rows]
    int rows)
{
    int r = blockIdx.x * blockDim.x + threadIdx.x;
    if (r >= rows) return;
    const float eps = 1e-6f;
    const float* p = pos + (size_t)r * 111;  // 37*3
    float Nx = p[0], Ny = p[1], Nz = p[2];
    float Ax = p[3], Ay = p[4], Az = p[5];
    float Cx = p[6], Cy = p[7], Cz = p[8];
    float nx = Nx - Ax, ny = Ny - Ay, nz = Nz - Az;
    float cx = Cx - Ax, cy = Cy - Ay, cz = Cz - Az;

    float n1 = sqrtf(eps + cx * cx + cy * cy);
    float s1 = -cy / n1, c1 = cx / n1;
    float n2 = sqrtf(eps + cx * cx + cy * cy + cz * cz);
    float s2 = cz / n2, c2 = sqrtf(cx * cx + cy * cy) / n2;

    // c_rots = c2 @ c1
    float r00 = c2 * c1, r01 = -c2 * s1, r02 = s2;
    float r10 = s1,      r11 = c1,       r12 = 0.f;
    float r20 = -s2 * c1, r21 = s2 * s1, r22 = c2;

    float nyp = r10 * nx + r11 * ny;                 // r12 == 0
    float nzp = r20 * nx + r21 * ny + r22 * nz;
    float n3 = sqrtf(eps + nyp * nyp + nzp * nzp);
    float sn = -nzp / n3, cn = nyp / n3;

    // M = nr @ c_rots ; reference returns rots = M^T, and einsum applies rots^T = M
    float* M = g_M + (size_t)r * 9;
    M[0] = r00; M[1] = r01; M[2] = r02;
    M[3] = cn * r10 - sn * r20; M[4] = cn * r11 - sn * r21; M[5] = cn * r12 - sn * r22;
    M[6] = sn * r10 + cn * r20; M[7] = sn * r11 + cn * r21; M[8] = sn * r12 + cn * r22;

    float fm = aamask[(size_t)r * 37 + 0] * aamask[(size_t)r * 37 + 1] * aamask[(size_t)r * 37 + 2];
    float* PJ = g_PJ + (size_t)r * 12;
    PJ[0] = pb[(size_t)r * 3 + 0];
    PJ[1] = pb[(size_t)r * 3 + 1];
    PJ[2] = pb[(size_t)r * 3 + 2];
    PJ[3] = Ax; PJ[4] = Ay; PJ[5] = Az;
    PJ[6] = pbm[r];
    PJ[7] = fm;
    PJ[8] = __int_as_float(aatype[r]);
    PJ[9] = 0.f; PJ[10] = 0.f; PJ[11] = 0.f;
}

__device__ __forceinline__ float lw(int k) {
    float v = 3.25f + 1.25f * (float)k;   // exact in fp32 (multiples of 0.25)
    return v * v;
}

__global__ __launch_bounds__(256) void main_kernel(
    const float* __restrict__ w,    // [64, 88]
    const float* __restrict__ bias, // [64]
    float* __restrict__ out)        // [rows, 768, 64]
{
    __shared__ float Wt[88 * 64];       // Wt[c*64 + o]
    __shared__ float stage[256 * 9];    // per-j scalars, stride 9 (conflict-free)
    __shared__ float rowdat[18];

    const int tid = threadIdx.x;
    const int row = blockIdx.x;         // t*N_RES + i
    const int t   = row / N_RES;

    // Load W transposed into smem
    for (int idx = tid; idx < 88 * 64; idx += 256) {
        int c = idx >> 6, o = idx & 63;
        Wt[idx] = w[o * 88 + c];
    }
    if (tid == 0) {
        const float* M = g_M + (size_t)row * 9;
        #pragma unroll
        for (int k = 0; k < 9; k++) rowdat[k] = M[k];
        const float* PI = g_PJ + (size_t)row * 12;
        #pragma unroll
        for (int k = 0; k < 9; k++) rowdat[9 + k] = PI[k];
    }
    __syncthreads();

    const float m00 = rowdat[0], m01 = rowdat[1], m02 = rowdat[2];
    const float m10 = rowdat[3], m11 = rowdat[4], m12 = rowdat[5];
    const float m20 = rowdat[6], m21 = rowdat[7], m22 = rowdat[8];
    const float pbix = rowdat[9],  pbiy = rowdat[10], pbiz = rowdat[11];
    const float caix = rowdat[12], caiy = rowdat[13], caiz = rowdat[14];
    const float pbmi = rowdat[15], fmi = rowdat[16];
    const int   aai  = __float_as_int(rowdat[17]);

    const int o4 = tid & 15;            // which group of 4 output channels
    const float4* Wt4 = (const float4*)Wt;
    const float4 c39  = Wt4[39 * 16 + o4];
    const float4 cAAi = Wt4[(62 + aai) * 16 + o4];
    const float4 c84  = Wt4[84 * 16 + o4];
    const float4 c85  = Wt4[85 * 16 + o4];
    const float4 c86  = Wt4[86 * 16 + o4];
    const float4 c87  = Wt4[87 * 16 + o4];
    const float4 bia  = ((const float4*)bias)[o4];

    const size_t outbase = (size_t)row * N_RES * 64;
    const float* PJbase = g_PJ + (size_t)t * N_RES * 12;

    for (int jt = 0; jt < N_RES; jt += 256) {
        // ---- Phase A: per-j scalars (one j per thread) ----
        {
            const int j = jt + tid;
            const float* PJ = PJbase + (size_t)j * 12;
            const float4 a0 = *(const float4*)(PJ);      // pbx,pby,pbz,cax
            const float4 a1 = *(const float4*)(PJ + 4);  // cay,caz,pbm,fm
            const float  aaf = PJ[8];

            float dx = a0.x - pbix, dy = a0.y - pbiy, dz = a0.z - pbiz;
            float d2 = dx * dx + dy * dy + dz * dz;

            // bin: analytic guess + exact-boundary fixups (strict comparisons)
            int k = (int)floorf((sqrtf(d2) - 3.25f) * 0.8f);
            k = max(-1, min(38, k));
            if (k >= 0 && d2 <= lw(k)) k--;
            if (k >= 0 && d2 <= lw(k)) k--;
            if (k < 38 && d2 >= lw(k + 1)) k++;
            if (k < 38 && d2 >= lw(k + 1)) k++;
            bool valid = (k >= 0) && (d2 > lw(k)) &&
                         (d2 < ((k < 38) ? lw(k + 1) : 1e8f));
            int bin = valid ? k : -1;

            float tx = a0.w - caix, ty = a1.x - caiy, tz = a1.y - caiz;
            float rvx = m00 * tx + m01 * ty + m02 * tz;
            float rvy = m10 * tx + m11 * ty + m12 * tz;
            float rvz = m20 * tx + m21 * ty + m22 * tz;
            float inv = rsqrtf(1e-6f + rvx * rvx + rvy * rvy + rvz * rvz);

            float* st = stage + tid * 9;
            st[0] = rvx * inv;
            st[1] = rvy * inv;
            st[2] = rvz * inv;
            st[3] = a1.z * pbmi;                 // pbm2
            st[4] = a1.w * fmi;                  // fm2d
            st[5] = __int_as_float(bin);
            st[6] = aaf;                          // aa_j bits
        }
        __syncthreads();

        // ---- Phase B: 16 passes, 16 threads per j, 4 channels per thread ----
        #pragma unroll 4
        for (int p = 0; p < 16; p++) {
            const int jj = p * 16 + (tid >> 4);
            const float* st = stage + jj * 9;
            float ux = st[0], uy = st[1], uz = st[2];
            float pbm2 = st[3], fm2 = st[4];
            int bin = __float_as_int(st[5]);
            int aaj = __float_as_int(st[6]);

            float4 wj = Wt4[(40 + aaj) * 16 + o4];
            float4 s;
            s.x = wj.x + cAAi.x + c87.x + c39.x * pbm2 + c84.x * ux + c85.x * uy + c86.x * uz;
            s.y = wj.y + cAAi.y + c87.y + c39.y * pbm2 + c84.y * ux + c85.y * uy + c86.y * uz;
            s.z = wj.z + cAAi.z + c87.z + c39.z * pbm2 + c84.z * ux + c85.z * uy + c86.z * uz;
            s.w = wj.w + cAAi.w + c87.w + c39.w * pbm2 + c84.w * ux + c85.w * uy + c86.w * uz;
            if (bin >= 0) {
                float4 wb = Wt4[bin * 16 + o4];
                s.x += wb.x; s.y += wb.y; s.z += wb.z; s.w += wb.w;
            }
            float4 r;
            r.x = bia.x + fm2 * s.x;
            r.y = bia.y + fm2 * s.y;
            r.z = bia.z + fm2 * s.z;
            r.w = bia.w + fm2 * s.w;
            *(float4*)(out + outbase + (size_t)(jt + jj) * 64 + o4 * 4) = r;
        }
        __syncthreads();
    }
}

extern "C" void kernel_launch(void* const* d_in, const int* in_sizes, int n_in,
                              void* d_out, int out_size)
{
    const float* pos    = (const float*)d_in[0];  // [t, n, 37, 3]
    const float* pb     = (const float*)d_in[1];  // [t, n, 3]
    const float* pbmask = (const float*)d_in[2];  // [t, n]
    const float* aamask = (const float*)d_in[3];  // [t, n, 37]
    const int*   aatype = (const int*)d_in[4];    // [t, n]
    const float* w      = (const float*)d_in[5];  // [64, 88]
    const float* b      = (const float*)d_in[6];  // [64]

    int rows = in_sizes[4];                       // t * n_res

    precompute_kernel<<<(rows + 255) / 256, 256>>>(pos, pb, pbmask, aamask, aatype, rows);
    main_kernel<<<rows, 256>>>(w, b, (float*)d_out);
}

// round 4
// speedup vs baseline: 1.0965x; 1.0965x over previous
#include <cuda_runtime.h>
#include <cstdint>

// TemplatePairEmbedderMonomer — write-bound sparse-linear formulation.
// out[t,i,j,o] = b[o] + fm2d * ( W[o,bin(i,j)] + W[o,39]*pbm2 + W[o,40+aa_j]
//                              + W[o,62+aa_i] + W[o,84:87]·uv + W[o,87] )

#define N_RES 768
#define MAX_ROWS 8192

// Scratch (no dynamic allocation allowed)
__device__ float g_M[MAX_ROWS * 9];    // per-row rotation M (rigid_vec = M @ (ca_j - ca_i))
__device__ float g_PJ[MAX_ROWS * 12];  // {pbx,pby,pbz, cax,cay,caz, pbm, fm, aa_bits, pad}

__global__ __launch_bounds__(256) void precompute_kernel(
    const float* __restrict__ pos,      // [rows, 37, 3]
    const float* __restrict__ pb,       // [rows, 3]
    const float* __restrict__ pbm,      // [rows]
    const float* __restrict__ aamask,   // [rows, 37]
    const int*   __restrict__ aatype,   // [rows]
    int rows)
{
    int r = blockIdx.x * blockDim.x + threadIdx.x;
    if (r >= rows) return;
    const float eps = 1e-6f;
    const float* p = pos + (size_t)r * 111;  // 37*3
    float Nx = p[0], Ny = p[1], Nz = p[2];
    float Ax = p[3], Ay = p[4], Az = p[5];
    float Cx = p[6], Cy = p[7], Cz = p[8];
    float nx = Nx - Ax, ny = Ny - Ay, nz = Nz - Az;
    float cx = Cx - Ax, cy = Cy - Ay, cz = Cz - Az;

    float n1 = sqrtf(eps + cx * cx + cy * cy);
    float s1 = -cy / n1, c1 = cx / n1;
    float n2 = sqrtf(eps + cx * cx + cy * cy + cz * cz);
    float s2 = cz / n2, c2 = sqrtf(cx * cx + cy * cy) / n2;

    // c_rots = c2 @ c1
    float r00 = c2 * c1, r01 = -c2 * s1, r02 = s2;
    float r10 = s1,      r11 = c1,       r12 = 0.f;
    float r20 = -s2 * c1, r21 = s2 * s1, r22 = c2;

    float nyp = r10 * nx + r11 * ny;                 // r12 == 0
    float nzp = r20 * nx + r21 * ny + r22 * nz;
    float n3 = sqrtf(eps + nyp * nyp + nzp * nzp);
    float sn = -nzp / n3, cn = nyp / n3;

    // M = nr @ c_rots ; reference returns rots = M^T, and einsum applies rots^T = M
    float* M = g_M + (size_t)r * 9;
    M[0] = r00; M[1] = r01; M[2] = r02;
    M[3] = cn * r10 - sn * r20; M[4] = cn * r11 - sn * r21; M[5] = cn * r12 - sn * r22;
    M[6] = sn * r10 + cn * r20; M[7] = sn * r11 + cn * r21; M[8] = sn * r12 + cn * r22;

    float fm = aamask[(size_t)r * 37 + 0] * aamask[(size_t)r * 37 + 1] * aamask[(size_t)r * 37 + 2];
    float* PJ = g_PJ + (size_t)r * 12;
    PJ[0] = pb[(size_t)r * 3 + 0];
    PJ[1] = pb[(size_t)r * 3 + 1];
    PJ[2] = pb[(size_t)r * 3 + 2];
    PJ[3] = Ax; PJ[4] = Ay; PJ[5] = Az;
    PJ[6] = pbm[r];
    PJ[7] = fm;
    PJ[8] = __int_as_float(aatype[r]);
    PJ[9] = 0.f; PJ[10] = 0.f; PJ[11] = 0.f;
}

__device__ __forceinline__ float lw(int k) {
    float v = 3.25f + 1.25f * (float)k;   // exact in fp32 (multiples of 0.25)
    return v * v;
}

__global__ __launch_bounds__(256, 4) void main_kernel(
    const float* __restrict__ w,    // [64, 88]
    const float* __restrict__ bias, // [64]
    float* __restrict__ out)        // [rows, 768, 64]
{
    __shared__ float Wt[88 * 64];       // Wt[c*64 + o]
    __shared__ float stage[256 * 8];    // per-j scalars, stride 8 (float4-friendly)
    __shared__ float rowdat[18];

    const int tid = threadIdx.x;
    const int row = blockIdx.x;         // t*N_RES + i
    const int t   = row / N_RES;

    // Load W transposed into smem
    for (int idx = tid; idx < 88 * 64; idx += 256) {
        int c = idx >> 6, o = idx & 63;
        Wt[idx] = w[o * 88 + c];
    }
    if (tid == 0) {
        const float* M = g_M + (size_t)row * 9;
        #pragma unroll
        for (int k = 0; k < 9; k++) rowdat[k] = M[k];
        const float* PI = g_PJ + (size_t)row * 12;
        #pragma unroll
        for (int k = 0; k < 9; k++) rowdat[9 + k] = PI[k];
    }
    __syncthreads();

    const float m00 = rowdat[0], m01 = rowdat[1], m02 = rowdat[2];
    const float m10 = rowdat[3], m11 = rowdat[4], m12 = rowdat[5];
    const float m20 = rowdat[6], m21 = rowdat[7], m22 = rowdat[8];
    const float pbix = rowdat[9],  pbiy = rowdat[10], pbiz = rowdat[11];
    const float caix = rowdat[12], caiy = rowdat[13], caiz = rowdat[14];
    const float pbmi = rowdat[15], fmi = rowdat[16];
    const int   aai  = __float_as_int(rowdat[17]);

    const int o4 = tid & 15;            // which group of 4 output channels
    const float4* Wt4 = (const float4*)Wt;
    const float4 c39 = Wt4[39 * 16 + o4];
    const float4 c84 = Wt4[84 * 16 + o4];
    const float4 c85 = Wt4[85 * 16 + o4];
    const float4 c86 = Wt4[86 * 16 + o4];
    float4 cFix;                        // W[:,62+aa_i] + W[:,87]
    {
        const float4 a = Wt4[(62 + aai) * 16 + o4];
        const float4 b87 = Wt4[87 * 16 + o4];
        cFix.x = a.x + b87.x; cFix.y = a.y + b87.y;
        cFix.z = a.z + b87.z; cFix.w = a.w + b87.w;
    }
    const float4 bia = ((const float4*)bias)[o4];

    float* outp = out + (size_t)row * N_RES * 64 + (size_t)(o4 * 4);
    const float* PJbase = g_PJ + (size_t)t * N_RES * 12;

    for (int jt = 0; jt < N_RES; jt += 256) {
        // ---- Phase A: per-j scalars (one j per thread) ----
        {
            const int j = jt + tid;
            const float* PJ = PJbase + (size_t)j * 12;
            const float4 a0 = *(const float4*)(PJ);      // pbx,pby,pbz,cax
            const float4 a1 = *(const float4*)(PJ + 4);  // cay,caz,pbm,fm
            const float  aaf = PJ[8];

            float dx = a0.x - pbix, dy = a0.y - pbiy, dz = a0.z - pbiz;
            float d2 = dx * dx + dy * dy + dz * dz;

            // bin: analytic guess + exact-boundary fixups (strict comparisons)
            int k = (int)floorf((sqrtf(d2) - 3.25f) * 0.8f);
            k = max(-1, min(38, k));
            if (k >= 0 && d2 <= lw(k)) k--;
            if (k >= 0 && d2 <= lw(k)) k--;
            if (k < 38 && d2 >= lw(k + 1)) k++;
            if (k < 38 && d2 >= lw(k + 1)) k++;
            bool valid = (k >= 0) && (d2 > lw(k)) &&
                         (d2 < ((k < 38) ? lw(k + 1) : 1e8f));
            int bin = valid ? k : -1;

            float tx = a0.w - caix, ty = a1.x - caiy, tz = a1.y - caiz;
            float rvx = m00 * tx + m01 * ty + m02 * tz;
            float rvy = m10 * tx + m11 * ty + m12 * tz;
            float rvz = m20 * tx + m21 * ty + m22 * tz;
            float inv = rsqrtf(1e-6f + rvx * rvx + rvy * rvy + rvz * rvz);

            float4 s0, s1;
            s0.x = rvx * inv;
            s0.y = rvy * inv;
            s0.z = rvz * inv;
            s0.w = a1.z * pbmi;                  // pbm2
            s1.x = a1.w * fmi;                   // fm2d
            s1.y = __int_as_float(bin);
            s1.z = aaf;                           // aa_j bits
            s1.w = 0.f;
            float4* st = (float4*)(stage + tid * 8);
            st[0] = s0;
            st[1] = s1;
        }
        __syncthreads();

        // ---- Phase B: 16 passes, 16 threads per j, 4 channels per thread ----
        #pragma unroll 4
        for (int p = 0; p < 16; p++) {
            const int jj = p * 16 + (tid >> 4);
            const float4* st = (const float4*)(stage + jj * 8);
            const float4 v0 = st[0];    // ux,uy,uz,pbm2
            const float4 v1 = st[1];    // fm2,bin,aaj,-
            const int bin = __float_as_int(v1.y);
            const int aaj = __float_as_int(v1.z);

            float4 wj = Wt4[(40 + aaj) * 16 + o4];
            float4 s;
            s.x = wj.x + cFix.x + c39.x * v0.w + c84.x * v0.x + c85.x * v0.y + c86.x * v0.z;
            s.y = wj.y + cFix.y + c39.y * v0.w + c84.y * v0.x + c85.y * v0.y + c86.y * v0.z;
            s.z = wj.z + cFix.z + c39.z * v0.w + c84.z * v0.x + c85.z * v0.y + c86.z * v0.z;
            s.w = wj.w + cFix.w + c39.w * v0.w + c84.w * v0.x + c85.w * v0.y + c86.w * v0.z;
            if (bin >= 0) {
                float4 wb = Wt4[bin * 16 + o4];
                s.x += wb.x; s.y += wb.y; s.z += wb.z; s.w += wb.w;
            }
            float4 r;
            r.x = bia.x + v1.x * s.x;
            r.y = bia.y + v1.x * s.y;
            r.z = bia.z + v1.x * s.z;
            r.w = bia.w + v1.x * s.w;
            __stcs((float4*)(outp + (size_t)(jt + jj) * 64), r);
        }
        __syncthreads();
    }
}

extern "C" void kernel_launch(void* const* d_in, const int* in_sizes, int n_in,
                              void* d_out, int out_size)
{
    const float* pos    = (const float*)d_in[0];  // [t, n, 37, 3]
    const float* pb     = (const float*)d_in[1];  // [t, n, 3]
    const float* pbmask = (const float*)d_in[2];  // [t, n]
    const float* aamask = (const float*)d_in[3];  // [t, n, 37]
    const int*   aatype = (const int*)d_in[4];    // [t, n]
    const float* w      = (const float*)d_in[5];  // [64, 88]
    const float* b      = (const float*)d_in[6];  // [64]

    int rows = in_sizes[4];                       // t * n_res

    precompute_kernel<<<(rows + 255) / 256, 256>>>(pos, pb, pbmask, aamask, aatype, rows);
    main_kernel<<<rows, 256>>>(w, b, (float*)d_out);
}